// round 14
// baseline (speedup 1.0000x reference)
#include <cuda_runtime.h>
#include <cuda_fp16.h>
#include <cstdint>

#define NPTS 50000
#define CH_IN 512
#define PP 128
#define KNB 27
#define EPSV 1e-5f

typedef __half half_t;

#define NROWT ((NPTS + 127) / 128)   // 391 row tiles

// ---------------- scratch (device globals) ----------------------------------
__device__ float  g_bufA[(size_t)NPTS * PP];
__device__ half_t g_xh[(size_t)NPTS * CH_IN];
__device__ half_t g_hh[(size_t)NPTS * PP];
__device__ half_t g_w1h[PP * CH_IN];        // [128 n][512 k]
__device__ half_t g_w2h[PP * KNB * PP];     // [128 n][3456 k]
__device__ half_t g_w3h[CH_IN * PP];        // [512 n][128 k]
__device__ float  g_ratio[NPTS];
__device__ float  g_m2[NPTS];
__device__ float2 g_part2[(size_t)NROWT * CH_IN];
__device__ float  g_mu[CH_IN];
__device__ float  g_rs[CH_IN];

// ---------------- PTX helpers ------------------------------------------------
__device__ __forceinline__ uint32_t smem_u32(const void* p) {
    uint32_t a;
    asm("{ .reg .u64 t; cvta.to.shared.u64 t, %1; cvt.u32.u64 %0, t; }" : "=r"(a) : "l"(p));
    return a;
}
#define CP16(dst, src) asm volatile("cp.async.cg.shared.global [%0], [%1], 16;" :: "r"(dst), "l"(src) : "memory")
#define CP_COMMIT()    asm volatile("cp.async.commit_group;" ::: "memory")
#define CP_WAIT0()     asm volatile("cp.async.wait_group 0;" ::: "memory")
#define CP_WAIT1()     asm volatile("cp.async.wait_group 1;" ::: "memory")

__device__ __forceinline__ void ldm4(uint32_t* r, uint32_t a) {
    asm volatile("ldmatrix.sync.aligned.m8n8.x4.shared.b16 {%0,%1,%2,%3}, [%4];"
                 : "=r"(r[0]), "=r"(r[1]), "=r"(r[2]), "=r"(r[3]) : "r"(a));
}
__device__ __forceinline__ void mma16816(float* c, const uint32_t* a, const uint32_t* b) {
    asm volatile("mma.sync.aligned.m16n8k16.row.col.f32.f16.f16.f32 "
                 "{%0,%1,%2,%3}, {%4,%5,%6,%7}, {%8,%9}, {%0,%1,%2,%3};"
                 : "+f"(c[0]), "+f"(c[1]), "+f"(c[2]), "+f"(c[3])
                 : "r"(a[0]), "r"(a[1]), "r"(a[2]), "r"(a[3]), "r"(b[0]), "r"(b[1]));
}

// ---------------- prep kernels ------------------------------------------------
// prep_main: ratio/m2/mout + x->fp16 + W1 (needed before GEMM1)
// prep_w23:  W2/W3 conversions (side stream; only needed before GEMM2/GEMM3)
#define NBR_B  ((NPTS + 255) / 256)
#define XC_B   ((int)(((size_t)NPTS * CH_IN / 4 + 255) / 256))
#define W1E (PP * CH_IN)
#define W2E (PP * KNB * PP)
#define W3E (CH_IN * PP)
#define W1_B ((W1E + 255) / 256)
#define W23_B ((W2E + W3E + 255) / 256)

__global__ void prep_main(const float* __restrict__ x, const float* __restrict__ mask,
                          const int* __restrict__ nbr, const float* __restrict__ W1,
                          float* __restrict__ mout) {
    int b = blockIdx.x;
    if (b < NBR_B) {
        int n = b * 256 + threadIdx.x;
        if (n >= NPTS) return;
        float s = 0.f;
#pragma unroll
        for (int k = 0; k < KNB; k++) s += mask[nbr[(size_t)n * KNB + k]];
        float has = s > 0.f ? 1.f : 0.f;
        g_ratio[n] = has * (27.f / fmaxf(s, 1.f));
        g_m2[n] = has;
        mout[n] = fminf(has + mask[n], 1.f);
    } else if (b < NBR_B + XC_B) {
        size_t j = ((size_t)(b - NBR_B) * 256 + threadIdx.x) * 4;
        if (j >= (size_t)NPTS * CH_IN) return;
        float4 v = *(const float4*)(x + j);
        *(half2*)(g_xh + j)     = __floats2half2_rn(v.x, v.y);
        *(half2*)(g_xh + j + 2) = __floats2half2_rn(v.z, v.w);
    } else {
        int i = (b - NBR_B - XC_B) * 256 + threadIdx.x;
        if (i < W1E) {
            int n = i / CH_IN, k = i % CH_IN;
            g_w1h[i] = __float2half_rn(W1[(size_t)k * PP + n]);
        }
    }
}
__global__ void prep_w23(const float* __restrict__ W2, const float* __restrict__ W3) {
    int i = blockIdx.x * 256 + threadIdx.x;
    if (i < W2E) {
        int n = i / (KNB * PP), kk = i % (KNB * PP);
        g_w2h[i] = __float2half_rn(W2[(size_t)kk * PP + n]);
    } else if (i < W2E + W3E) {
        int j = i - W2E;
        int n = j / PP, k = j % PP;
        g_w3h[j] = __float2half_rn(W3[(size_t)k * CH_IN + n]);
    }
}

// ---------------- other small kernels ----------------------------------------
__global__ void stats_finalp(const float2* __restrict__ part, int C, int M, int nslots) {
    int c = blockIdx.x;
    int tid = threadIdx.x;
    float s = 0.f, q = 0.f;
    for (int r = tid; r < nslots; r += 256) {
        float2 v = part[(size_t)r * C + c];
        s += v.x; q += v.y;
    }
    __shared__ float ss[256], sq[256];
    ss[tid] = s; sq[tid] = q;
    __syncthreads();
    for (int d = 128; d > 0; d >>= 1) {
        if (tid < d) { ss[tid] += ss[tid + d]; sq[tid] += sq[tid + d]; }
        __syncthreads();
    }
    if (tid == 0) {
        float mu = ss[0] / (float)M;
        float var = sq[0] / (float)M - mu * mu;
        g_mu[c] = mu;
        g_rs[c] = rsqrtf(fmaxf(var, 0.f) + EPSV);
    }
}
__global__ void ew_split(const float* __restrict__ in, const float* __restrict__ mask) {
    int j = (blockIdx.x * blockDim.x + threadIdx.x) * 4;
    if (j >= NPTS * PP) return;
    int c = j & (PP - 1);
    int n = j >> 7;
    float mv = mask ? mask[n] : 1.f;
    float4 v = *(const float4*)(in + j);
    float o0 = (v.x - g_mu[c + 0]) * g_rs[c + 0];
    float o1 = (v.y - g_mu[c + 1]) * g_rs[c + 1];
    float o2 = (v.z - g_mu[c + 2]) * g_rs[c + 2];
    float o3 = (v.w - g_mu[c + 3]) * g_rs[c + 3];
    o0 = (o0 >= 0.f ? o0 : 0.1f * o0) * mv;
    o1 = (o1 >= 0.f ? o1 : 0.1f * o1) * mv;
    o2 = (o2 >= 0.f ? o2 : 0.1f * o2) * mv;
    o3 = (o3 >= 0.f ? o3 : 0.1f * o3) * mv;
    *(half2*)(g_hh + j)     = __floats2half2_rn(o0, o1);
    *(half2*)(g_hh + j + 2) = __floats2half2_rn(o2, o3);
}
__global__ void ew_final(const float* __restrict__ x, float* __restrict__ outp) {
    size_t j = ((size_t)blockIdx.x * blockDim.x + threadIdx.x) * 4;
    if (j >= (size_t)NPTS * CH_IN) return;
    int c = (int)(j & (CH_IN - 1));
    float4 t = *(const float4*)(outp + j);
    float4 xv = *(const float4*)(x + j);
    float4 o;
    o.x = (t.x - g_mu[c + 0]) * g_rs[c + 0] + xv.x;
    o.y = (t.y - g_mu[c + 1]) * g_rs[c + 1] + xv.y;
    o.z = (t.z - g_mu[c + 2]) * g_rs[c + 2] + xv.z;
    o.w = (t.w - g_mu[c + 3]) * g_rs[c + 3] + xv.w;
    o.x = o.x >= 0.f ? o.x : 0.1f * o.x;
    o.y = o.y >= 0.f ? o.y : 0.1f * o.y;
    o.z = o.z >= 0.f ? o.z : 0.1f * o.z;
    o.w = o.w >= 0.f ? o.w : 0.1f * o.w;
    *(float4*)(outp + j) = o;
}

// ---------------- HMMA GEMM (protected config) -------------------------------
// C[M,N] = A[M,Kd] @ B[N,Kd]^T, fp16 operands, fp32 acc.
// 128x128 CTA tile, 8 warps of 64x32, K-chunk 64, 3-stage cp.async, 2 CTAs/SM.
// Gather path: snbr caches precomputed ELEMENT OFFSETS (nbr*lda, fits u32).
#define STAGE_BYTES 32768
#define OFF_B  16384u
#define OFF_SN (3u * STAGE_BYTES)
#define SMEM_DYN (3 * STAGE_BYTES + 128 * KNB * 4)

__global__ __launch_bounds__(256, 2) void mma_gemm(
    const half_t* __restrict__ Ah, int lda,
    const int* __restrict__ nbr,
    const half_t* __restrict__ Bh, int ldb,
    float* __restrict__ C, int ldc, int M, int Kd,
    const float* __restrict__ rowscale,
    float2* __restrict__ part, int partC) {
    extern __shared__ char smem[];
    const uint32_t sb = smem_u32(smem);
    const int tid = threadIdx.x;
    const int row0 = blockIdx.y * 128;
    const int col0 = blockIdx.x * 128;
    uint32_t* snbr = (uint32_t*)(smem + OFF_SN);

    if (nbr) {
        for (int i = tid; i < 128 * KNB; i += 256) {
            int r = i / KNB, k = i - r * KNB;
            int gr = row0 + r;
            snbr[i] = (gr < M) ? (uint32_t)nbr[(size_t)gr * KNB + k] * (uint32_t)lda : 0u;
        }
        __syncthreads();
    }

    const int w = tid >> 5, l = tid & 31;
    const int wm = (w & 1) * 64, wn = (w >> 1) * 32;
    const int a7 = l & 7;
    const int lkA = (l >> 4) & 1, lkB = (l >> 3) & 1;
    uint32_t aRow[4], bRow[2];
#pragma unroll
    for (int i = 0; i < 4; i++) aRow[i] = (uint32_t)(wm + 16 * i + (l & 15)) << 7;
#pragma unroll
    for (int j = 0; j < 2; j++) bRow[j] = (uint32_t)(wn + 16 * j + (l & 7) + ((l & 16) >> 1)) << 7;

    float acc[4][4][4];
#pragma unroll
    for (int i = 0; i < 4; i++)
#pragma unroll
        for (int n = 0; n < 4; n++)
#pragma unroll
            for (int q = 0; q < 4; q++) acc[i][n][q] = 0.f;

    const int nch = Kd >> 6;

    // per-thread invariant load-loop bases (4 iterations of i = tid + p*256)
    const int r0i = tid >> 3, seg0 = tid & 7;            // + p*32 rows
    uint32_t swoff[4];
    const half_t* aBase[4];
    const half_t* bBase[4];
#pragma unroll
    for (int p = 0; p < 4; p++) {
        const int r = r0i + p * 32;
        swoff[p] = ((uint32_t)r << 7) + (uint32_t)((seg0 ^ (r & 7)) << 4);
        aBase[p] = Ah + (size_t)min(row0 + r, M - 1) * (size_t)lda + (seg0 << 3);
        bBase[p] = Bh + (size_t)(col0 + r) * (size_t)ldb + (seg0 << 3);
    }
    const half_t* aGatherBase = Ah + (seg0 << 3);

    auto load_chunk = [&](int ch, int stage) {
        const int k0 = ch << 6;
        const int kn = ch >> 1;
        const int c0 = (ch & 1) << 6;
        const uint32_t sbase = sb + (uint32_t)stage * STAGE_BYTES;
#pragma unroll
        for (int p = 0; p < 4; p++) {
            const uint32_t sw = sbase + swoff[p];
            if (nbr) {
                const int r = r0i + p * 32;
                CP16(sw, aGatherBase + snbr[r * KNB + kn] + c0);
            } else {
                CP16(sw, aBase[p] + k0);
            }
            CP16(sw + OFF_B, bBase[p] + k0);
        }
    };

    load_chunk(0, 0);
    CP_COMMIT();
    if (nch > 1) { load_chunk(1, 1); CP_COMMIT(); }

    for (int ch = 0; ch < nch; ch++) {
        if (ch + 1 < nch) CP_WAIT1(); else CP_WAIT0();
        __syncthreads();   // data visibility + WAR protection for next load
        if (ch + 2 < nch) { load_chunk(ch + 2, (ch + 2) % 3); CP_COMMIT(); }

        const uint32_t bA = sb + (uint32_t)(ch % 3) * STAGE_BYTES;
#pragma unroll
        for (int s = 0; s < 4; s++) {
            uint32_t ah[4][4], bh[2][4];
            const uint32_t kwA = (uint32_t)((s << 1) | lkA);
            const uint32_t kwB = (uint32_t)((s << 1) | lkB);
#pragma unroll
            for (int i = 0; i < 4; i++)
                ldm4(ah[i], bA + aRow[i] + ((kwA ^ (uint32_t)a7) << 4));
#pragma unroll
            for (int j = 0; j < 2; j++)
                ldm4(bh[j], bA + OFF_B + bRow[j] + ((kwB ^ (uint32_t)a7) << 4));
#pragma unroll
            for (int i = 0; i < 4; i++)
#pragma unroll
                for (int n = 0; n < 4; n++)
                    mma16816(acc[i][n], ah[i], &bh[n >> 1][(n & 1) * 2]);
        }
    }

    // ---- fused epilogue: scale, store, per-CTA column partial stats ----
    float csum[8], csq[8];
#pragma unroll
    for (int j = 0; j < 8; j++) { csum[j] = 0.f; csq[j] = 0.f; }
#pragma unroll
    for (int i = 0; i < 4; i++) {
#pragma unroll
        for (int hf = 0; hf < 2; hf++) {
            const int r = row0 + wm + 16 * i + 8 * hf + (l >> 2);
            const float sc = (r < M) ? rowscale[r] : 0.f;
            float* cp = C + (size_t)r * ldc + col0 + wn + 2 * (l & 3);
#pragma unroll
            for (int n = 0; n < 4; n++) {
                float v0 = acc[i][n][2 * hf] * sc;
                float v1 = acc[i][n][2 * hf + 1] * sc;
                csum[2 * n]     += v0; csq[2 * n]     += v0 * v0;
                csum[2 * n + 1] += v1; csq[2 * n + 1] += v1 * v1;
                if (r < M) *(float2*)(cp + 8 * n) = make_float2(v0, v1);
            }
        }
    }
#pragma unroll
    for (int d = 4; d < 32; d <<= 1) {
#pragma unroll
        for (int j = 0; j < 8; j++) {
            csum[j] += __shfl_xor_sync(0xFFFFFFFFu, csum[j], d);
            csq[j]  += __shfl_xor_sync(0xFFFFFFFFu, csq[j], d);
        }
    }
    float2* red = (float2*)(smem + OFF_SN);
    __syncthreads();
    if (l < 4) {
#pragma unroll
        for (int j = 0; j < 8; j++) {
            int col_local = 8 * (j >> 1) + 2 * l + (j & 1);
            red[w * 32 + col_local] = make_float2(csum[j], csq[j]);
        }
    }
    __syncthreads();
    if (tid < 128) {
        int c = tid, q = c >> 5, lo = c & 31;
        float2 a = red[(2 * q) * 32 + lo];
        float2 b = red[(2 * q + 1) * 32 + lo];
        part[(size_t)blockIdx.y * partC + col0 + c] = make_float2(a.x + b.x, a.y + b.y);
    }
}

// ---------------- launch ------------------------------------------------------
extern "C" void kernel_launch(void* const* d_in, const int* in_sizes, int n_in,
                              void* d_out, int out_size) {
    const float* x    = (const float*)d_in[0];
    const float* mask = (const float*)d_in[1];
    const int*   nbr  = (const int*)d_in[2];
    const float* W1   = (const float*)d_in[3];
    const float* W2   = (const float*)d_in[4];
    const float* W3   = (const float*)d_in[5];
    float* out  = (float*)d_out;
    float* mout = out + (size_t)NPTS * CH_IN;

    cudaFuncSetAttribute(mma_gemm, cudaFuncAttributeMaxDynamicSharedMemorySize, SMEM_DYN);

    static cudaStream_t sideStream = nullptr;
    static cudaEvent_t evFork = nullptr, evJoin = nullptr;
    if (!sideStream) {
        cudaStreamCreateWithFlags(&sideStream, cudaStreamNonBlocking);
        cudaEventCreateWithFlags(&evFork, cudaEventDisableTiming);
        cudaEventCreateWithFlags(&evJoin, cudaEventDisableTiming);
    }

    float *pA, *pRatio, *pM2;
    float2* pPart;
    half_t *pxh, *phh, *pw1h, *pw2h, *pw3h;
    cudaGetSymbolAddress((void**)&pA, g_bufA);
    cudaGetSymbolAddress((void**)&pRatio, g_ratio);
    cudaGetSymbolAddress((void**)&pM2, g_m2);
    cudaGetSymbolAddress((void**)&pPart, g_part2);
    cudaGetSymbolAddress((void**)&pxh, g_xh);
    cudaGetSymbolAddress((void**)&phh, g_hh);
    cudaGetSymbolAddress((void**)&pw1h, g_w1h);
    cudaGetSymbolAddress((void**)&pw2h, g_w2h);
    cudaGetSymbolAddress((void**)&pw3h, g_w3h);

    // fork: W2/W3 conversion on side stream, overlapping prep_main + GEMM1
    cudaEventRecord(evFork, 0);
    cudaStreamWaitEvent(sideStream, evFork, 0);
    prep_w23<<<W23_B, 256, 0, sideStream>>>(W2, W3);
    cudaEventRecord(evJoin, sideStream);

    // main stream: prep needed for GEMM1
    prep_main<<<NBR_B + XC_B + W1_B, 256>>>(x, mask, nbr, W1, mout);

    // conv1: t1 = (x @ W1) * mask   [Kd=512]
    mma_gemm<<<dim3(1, NROWT), 256, SMEM_DYN>>>(pxh, CH_IN, nullptr,
        pw1h, CH_IN, pA, PP, NPTS, CH_IN, mask, pPart, PP);
    stats_finalp<<<PP, 256>>>(pPart, PP, NPTS, NROWT);
    ew_split<<<(NPTS * PP / 4 + 255) / 256, 256>>>(pA, mask);

    // join before GEMM2 needs W2 (and GEMM3 needs W3)
    cudaStreamWaitEvent(0, evJoin, 0);

    // conv2 gathered: Kd = 27*128 = 3456
    mma_gemm<<<dim3(1, NROWT), 256, SMEM_DYN>>>(phh, PP, nbr,
        pw2h, KNB * PP, pA, PP, NPTS, KNB * PP, pRatio, pPart, PP);
    stats_finalp<<<PP, 256>>>(pPart, PP, NPTS, NROWT);
    ew_split<<<(NPTS * PP / 4 + 255) / 256, 256>>>(pA, nullptr);

    // conv3: out = (h2 @ W3) * m2   [N=512 via 4 column tiles, Kd=128]
    mma_gemm<<<dim3(4, NROWT), 256, SMEM_DYN>>>(phh, PP, nullptr,
        pw3h, PP, out, CH_IN, NPTS, PP, pM2, pPart, CH_IN);
    stats_finalp<<<CH_IN, 256>>>(pPart, CH_IN, NPTS, NROWT);
    ew_final<<<(int)(((size_t)NPTS * CH_IN / 4 + 255) / 256), 256>>>(x, out);
}

// round 15
// speedup vs baseline: 1.0041x; 1.0041x over previous
#include <cuda_runtime.h>
#include <cuda_fp16.h>
#include <cstdint>

#define NPTS 50000
#define CH_IN 512
#define PP 128
#define KNB 27
#define EPSV 1e-5f

typedef __half half_t;

#define NROWT ((NPTS + 127) / 128)   // 391 row tiles

// ---------------- scratch (device globals) ----------------------------------
__device__ float  g_bufA[(size_t)NPTS * PP];
__device__ half_t g_xh[(size_t)NPTS * CH_IN];
__device__ half_t g_hh[(size_t)NPTS * PP];
__device__ half_t g_w1h[PP * CH_IN];        // [128 n][512 k]
__device__ half_t g_w2h[PP * KNB * PP];     // [128 n][3456 k]
__device__ half_t g_w3h[CH_IN * PP];        // [512 n][128 k]
__device__ float  g_ratio[NPTS];
__device__ float  g_m2[NPTS];
__device__ float2 g_part2[(size_t)NROWT * CH_IN];
__device__ float  g_mu[CH_IN];
__device__ float  g_rs[CH_IN];

// ---------------- PTX helpers ------------------------------------------------
__device__ __forceinline__ uint32_t smem_u32(const void* p) {
    uint32_t a;
    asm("{ .reg .u64 t; cvta.to.shared.u64 t, %1; cvt.u32.u64 %0, t; }" : "=r"(a) : "l"(p));
    return a;
}
#define CP16(dst, src) asm volatile("cp.async.cg.shared.global [%0], [%1], 16;" :: "r"(dst), "l"(src) : "memory")
#define CP_COMMIT()    asm volatile("cp.async.commit_group;" ::: "memory")
#define CP_WAIT0()     asm volatile("cp.async.wait_group 0;" ::: "memory")
#define CP_WAIT1()     asm volatile("cp.async.wait_group 1;" ::: "memory")

__device__ __forceinline__ void ldm4(uint32_t* r, uint32_t a) {
    asm volatile("ldmatrix.sync.aligned.m8n8.x4.shared.b16 {%0,%1,%2,%3}, [%4];"
                 : "=r"(r[0]), "=r"(r[1]), "=r"(r[2]), "=r"(r[3]) : "r"(a));
}
__device__ __forceinline__ void mma16816(float* c, const uint32_t* a, const uint32_t* b) {
    asm volatile("mma.sync.aligned.m16n8k16.row.col.f32.f16.f16.f32 "
                 "{%0,%1,%2,%3}, {%4,%5,%6,%7}, {%8,%9}, {%0,%1,%2,%3};"
                 : "+f"(c[0]), "+f"(c[1]), "+f"(c[2]), "+f"(c[3])
                 : "r"(a[0]), "r"(a[1]), "r"(a[2]), "r"(a[3]), "r"(b[0]), "r"(b[1]));
}

// ---------------- fused prep kernel (serial, R13-proven) ----------------------
#define NBR_B  ((NPTS + 255) / 256)
#define XC_B   ((int)(((size_t)NPTS * CH_IN / 4 + 255) / 256))
#define W1E (PP * CH_IN)
#define W2E (PP * KNB * PP)
#define W3E (CH_IN * PP)
#define W_B  ((W1E + W2E + W3E + 255) / 256)

__global__ void prep_all(const float* __restrict__ x, const float* __restrict__ mask,
                         const int* __restrict__ nbr,
                         const float* __restrict__ W1, const float* __restrict__ W2,
                         const float* __restrict__ W3, float* __restrict__ mout) {
    int b = blockIdx.x;
    if (b < NBR_B) {
        int n = b * 256 + threadIdx.x;
        if (n >= NPTS) return;
        float s = 0.f;
#pragma unroll
        for (int k = 0; k < KNB; k++) s += mask[nbr[(size_t)n * KNB + k]];
        float has = s > 0.f ? 1.f : 0.f;
        g_ratio[n] = has * (27.f / fmaxf(s, 1.f));
        g_m2[n] = has;
        mout[n] = fminf(has + mask[n], 1.f);
    } else if (b < NBR_B + XC_B) {
        size_t j = ((size_t)(b - NBR_B) * 256 + threadIdx.x) * 4;
        if (j >= (size_t)NPTS * CH_IN) return;
        float4 v = *(const float4*)(x + j);
        *(half2*)(g_xh + j)     = __floats2half2_rn(v.x, v.y);
        *(half2*)(g_xh + j + 2) = __floats2half2_rn(v.z, v.w);
    } else {
        int i = (b - NBR_B - XC_B) * 256 + threadIdx.x;
        if (i < W1E) {
            int n = i / CH_IN, k = i % CH_IN;
            g_w1h[i] = __float2half_rn(W1[(size_t)k * PP + n]);
        } else if (i < W1E + W2E) {
            int j = i - W1E;
            int n = j / (KNB * PP), kk = j % (KNB * PP);
            g_w2h[j] = __float2half_rn(W2[(size_t)kk * PP + n]);
        } else if (i < W1E + W2E + W3E) {
            int j = i - W1E - W2E;
            int n = j / PP, k = j % PP;
            g_w3h[j] = __float2half_rn(W3[(size_t)k * CH_IN + n]);
        }
    }
}

// ---------------- other small kernels ----------------------------------------
__global__ void stats_finalp(const float2* __restrict__ part, int C, int M, int nslots) {
    int c = blockIdx.x;
    int tid = threadIdx.x;
    float s = 0.f, q = 0.f;
    for (int r = tid; r < nslots; r += 256) {
        float2 v = part[(size_t)r * C + c];
        s += v.x; q += v.y;
    }
    __shared__ float ss[256], sq[256];
    ss[tid] = s; sq[tid] = q;
    __syncthreads();
    for (int d = 128; d > 0; d >>= 1) {
        if (tid < d) { ss[tid] += ss[tid + d]; sq[tid] += sq[tid + d]; }
        __syncthreads();
    }
    if (tid == 0) {
        float mu = ss[0] / (float)M;
        float var = sq[0] / (float)M - mu * mu;
        g_mu[c] = mu;
        g_rs[c] = rsqrtf(fmaxf(var, 0.f) + EPSV);
    }
}
// norm + lrelu (+mask) -> fp16, 8 channels per thread
__global__ void ew_split(const float* __restrict__ in, const float* __restrict__ mask) {
    int j = (blockIdx.x * blockDim.x + threadIdx.x) * 8;
    if (j >= NPTS * PP) return;
    int c = j & (PP - 1);
    int n = j >> 7;
    float mv = mask ? mask[n] : 1.f;
#pragma unroll
    for (int h = 0; h < 2; h++) {
        float4 v = *(const float4*)(in + j + 4 * h);
        int cc = c + 4 * h;
        float o0 = (v.x - g_mu[cc + 0]) * g_rs[cc + 0];
        float o1 = (v.y - g_mu[cc + 1]) * g_rs[cc + 1];
        float o2 = (v.z - g_mu[cc + 2]) * g_rs[cc + 2];
        float o3 = (v.w - g_mu[cc + 3]) * g_rs[cc + 3];
        o0 = (o0 >= 0.f ? o0 : 0.1f * o0) * mv;
        o1 = (o1 >= 0.f ? o1 : 0.1f * o1) * mv;
        o2 = (o2 >= 0.f ? o2 : 0.1f * o2) * mv;
        o3 = (o3 >= 0.f ? o3 : 0.1f * o3) * mv;
        *(half2*)(g_hh + j + 4 * h)     = __floats2half2_rn(o0, o1);
        *(half2*)(g_hh + j + 4 * h + 2) = __floats2half2_rn(o2, o3);
    }
}
__global__ void ew_final(const float* __restrict__ x, float* __restrict__ outp) {
    size_t j = ((size_t)blockIdx.x * blockDim.x + threadIdx.x) * 4;
    if (j >= (size_t)NPTS * CH_IN) return;
    int c = (int)(j & (CH_IN - 1));
    float4 t = *(const float4*)(outp + j);
    float4 xv = *(const float4*)(x + j);
    float4 o;
    o.x = (t.x - g_mu[c + 0]) * g_rs[c + 0] + xv.x;
    o.y = (t.y - g_mu[c + 1]) * g_rs[c + 1] + xv.y;
    o.z = (t.z - g_mu[c + 2]) * g_rs[c + 2] + xv.z;
    o.w = (t.w - g_mu[c + 3]) * g_rs[c + 3] + xv.w;
    o.x = o.x >= 0.f ? o.x : 0.1f * o.x;
    o.y = o.y >= 0.f ? o.y : 0.1f * o.y;
    o.z = o.z >= 0.f ? o.z : 0.1f * o.z;
    o.w = o.w >= 0.f ? o.w : 0.1f * o.w;
    *(float4*)(outp + j) = o;
}

// ---------------- HMMA GEMM (protected config) -------------------------------
// C[M,N] = A[M,Kd] @ B[N,Kd]^T, fp16 operands, fp32 acc.
// 128x128 CTA tile, 8 warps of 64x32, K-chunk 64, 3-stage cp.async, 2 CTAs/SM.
// Gather path: snbr caches precomputed ELEMENT OFFSETS (nbr*lda, fits u32).
#define STAGE_BYTES 32768
#define OFF_B  16384u
#define OFF_SN (3u * STAGE_BYTES)
#define SMEM_DYN (3 * STAGE_BYTES + 128 * KNB * 4)

__global__ __launch_bounds__(256, 2) void mma_gemm(
    const half_t* __restrict__ Ah, int lda,
    const int* __restrict__ nbr,
    const half_t* __restrict__ Bh, int ldb,
    float* __restrict__ C, int ldc, int M, int Kd,
    const float* __restrict__ rowscale,
    float2* __restrict__ part, int partC) {
    extern __shared__ char smem[];
    const uint32_t sb = smem_u32(smem);
    const int tid = threadIdx.x;
    const int row0 = blockIdx.y * 128;
    const int col0 = blockIdx.x * 128;
    uint32_t* snbr = (uint32_t*)(smem + OFF_SN);

    if (nbr) {
        for (int i = tid; i < 128 * KNB; i += 256) {
            int r = i / KNB, k = i - r * KNB;
            int gr = row0 + r;
            snbr[i] = (gr < M) ? (uint32_t)nbr[(size_t)gr * KNB + k] * (uint32_t)lda : 0u;
        }
        __syncthreads();
    }

    const int w = tid >> 5, l = tid & 31;
    const int wm = (w & 1) * 64, wn = (w >> 1) * 32;
    const int a7 = l & 7;
    const int lkA = (l >> 4) & 1, lkB = (l >> 3) & 1;
    uint32_t aRow[4], bRow[2];
#pragma unroll
    for (int i = 0; i < 4; i++) aRow[i] = (uint32_t)(wm + 16 * i + (l & 15)) << 7;
#pragma unroll
    for (int j = 0; j < 2; j++) bRow[j] = (uint32_t)(wn + 16 * j + (l & 7) + ((l & 16) >> 1)) << 7;

    float acc[4][4][4];
#pragma unroll
    for (int i = 0; i < 4; i++)
#pragma unroll
        for (int n = 0; n < 4; n++)
#pragma unroll
            for (int q = 0; q < 4; q++) acc[i][n][q] = 0.f;

    const int nch = Kd >> 6;

    const int r0i = tid >> 3, seg0 = tid & 7;
    uint32_t swoff[4];
    const half_t* aBase[4];
    const half_t* bBase[4];
#pragma unroll
    for (int p = 0; p < 4; p++) {
        const int r = r0i + p * 32;
        swoff[p] = ((uint32_t)r << 7) + (uint32_t)((seg0 ^ (r & 7)) << 4);
        aBase[p] = Ah + (size_t)min(row0 + r, M - 1) * (size_t)lda + (seg0 << 3);
        bBase[p] = Bh + (size_t)(col0 + r) * (size_t)ldb + (seg0 << 3);
    }
    const half_t* aGatherBase = Ah + (seg0 << 3);

    auto load_chunk = [&](int ch, int stage) {
        const int k0 = ch << 6;
        const int kn = ch >> 1;
        const int c0 = (ch & 1) << 6;
        const uint32_t sbase = sb + (uint32_t)stage * STAGE_BYTES;
#pragma unroll
        for (int p = 0; p < 4; p++) {
            const uint32_t sw = sbase + swoff[p];
            if (nbr) {
                const int r = r0i + p * 32;
                CP16(sw, aGatherBase + snbr[r * KNB + kn] + c0);
            } else {
                CP16(sw, aBase[p] + k0);
            }
            CP16(sw + OFF_B, bBase[p] + k0);
        }
    };

    load_chunk(0, 0);
    CP_COMMIT();
    if (nch > 1) { load_chunk(1, 1); CP_COMMIT(); }

    for (int ch = 0; ch < nch; ch++) {
        if (ch + 1 < nch) CP_WAIT1(); else CP_WAIT0();
        __syncthreads();
        if (ch + 2 < nch) { load_chunk(ch + 2, (ch + 2) % 3); CP_COMMIT(); }

        const uint32_t bA = sb + (uint32_t)(ch % 3) * STAGE_BYTES;
#pragma unroll
        for (int s = 0; s < 4; s++) {
            uint32_t ah[4][4], bh[2][4];
            const uint32_t kwA = (uint32_t)((s << 1) | lkA);
            const uint32_t kwB = (uint32_t)((s << 1) | lkB);
#pragma unroll
            for (int i = 0; i < 4; i++)
                ldm4(ah[i], bA + aRow[i] + ((kwA ^ (uint32_t)a7) << 4));
#pragma unroll
            for (int j = 0; j < 2; j++)
                ldm4(bh[j], bA + OFF_B + bRow[j] + ((kwB ^ (uint32_t)a7) << 4));
#pragma unroll
            for (int i = 0; i < 4; i++)
#pragma unroll
                for (int n = 0; n < 4; n++)
                    mma16816(acc[i][n], ah[i], &bh[n >> 1][(n & 1) * 2]);
        }
    }

    // ---- fused epilogue: scale, store, per-CTA column partial stats ----
    float csum[8], csq[8];
#pragma unroll
    for (int j = 0; j < 8; j++) { csum[j] = 0.f; csq[j] = 0.f; }
#pragma unroll
    for (int i = 0; i < 4; i++) {
#pragma unroll
        for (int hf = 0; hf < 2; hf++) {
            const int r = row0 + wm + 16 * i + 8 * hf + (l >> 2);
            const float sc = (r < M) ? rowscale[r] : 0.f;
            float* cp = C + (size_t)r * ldc + col0 + wn + 2 * (l & 3);
#pragma unroll
            for (int n = 0; n < 4; n++) {
                float v0 = acc[i][n][2 * hf] * sc;
                float v1 = acc[i][n][2 * hf + 1] * sc;
                csum[2 * n]     += v0; csq[2 * n]     += v0 * v0;
                csum[2 * n + 1] += v1; csq[2 * n + 1] += v1 * v1;
                if (r < M) *(float2*)(cp + 8 * n) = make_float2(v0, v1);
            }
        }
    }
#pragma unroll
    for (int d = 4; d < 32; d <<= 1) {
#pragma unroll
        for (int j = 0; j < 8; j++) {
            csum[j] += __shfl_xor_sync(0xFFFFFFFFu, csum[j], d);
            csq[j]  += __shfl_xor_sync(0xFFFFFFFFu, csq[j], d);
        }
    }
    float2* red = (float2*)(smem + OFF_SN);
    __syncthreads();
    if (l < 4) {
#pragma unroll
        for (int j = 0; j < 8; j++) {
            int col_local = 8 * (j >> 1) + 2 * l + (j & 1);
            red[w * 32 + col_local] = make_float2(csum[j], csq[j]);
        }
    }
    __syncthreads();
    if (tid < 128) {
        int c = tid, q = c >> 5, lo = c & 31;
        float2 a = red[(2 * q) * 32 + lo];
        float2 b = red[(2 * q + 1) * 32 + lo];
        part[(size_t)blockIdx.y * partC + col0 + c] = make_float2(a.x + b.x, a.y + b.y);
    }
}

// ---------------- launch ------------------------------------------------------
extern "C" void kernel_launch(void* const* d_in, const int* in_sizes, int n_in,
                              void* d_out, int out_size) {
    const float* x    = (const float*)d_in[0];
    const float* mask = (const float*)d_in[1];
    const int*   nbr  = (const int*)d_in[2];
    const float* W1   = (const float*)d_in[3];
    const float* W2   = (const float*)d_in[4];
    const float* W3   = (const float*)d_in[5];
    float* out  = (float*)d_out;
    float* mout = out + (size_t)NPTS * CH_IN;

    cudaFuncSetAttribute(mma_gemm, cudaFuncAttributeMaxDynamicSharedMemorySize, SMEM_DYN);

    float *pA, *pRatio, *pM2;
    float2* pPart;
    half_t *pxh, *phh, *pw1h, *pw2h, *pw3h;
    cudaGetSymbolAddress((void**)&pA, g_bufA);
    cudaGetSymbolAddress((void**)&pRatio, g_ratio);
    cudaGetSymbolAddress((void**)&pM2, g_m2);
    cudaGetSymbolAddress((void**)&pPart, g_part2);
    cudaGetSymbolAddress((void**)&pxh, g_xh);
    cudaGetSymbolAddress((void**)&phh, g_hh);
    cudaGetSymbolAddress((void**)&pw1h, g_w1h);
    cudaGetSymbolAddress((void**)&pw2h, g_w2h);
    cudaGetSymbolAddress((void**)&pw3h, g_w3h);

    // fused prep (serial single stream, R13-proven)
    prep_all<<<NBR_B + XC_B + W_B, 256>>>(x, mask, nbr, W1, W2, W3, mout);

    // conv1: t1 = (x @ W1) * mask   [Kd=512]
    mma_gemm<<<dim3(1, NROWT), 256, SMEM_DYN>>>(pxh, CH_IN, nullptr,
        pw1h, CH_IN, pA, PP, NPTS, CH_IN, mask, pPart, PP);
    stats_finalp<<<PP, 256>>>(pPart, PP, NPTS, NROWT);
    ew_split<<<(NPTS * PP / 8 + 255) / 256, 256>>>(pA, mask);

    // conv2 gathered: Kd = 27*128 = 3456
    mma_gemm<<<dim3(1, NROWT), 256, SMEM_DYN>>>(phh, PP, nbr,
        pw2h, KNB * PP, pA, PP, NPTS, KNB * PP, pRatio, pPart, PP);
    stats_finalp<<<PP, 256>>>(pPart, PP, NPTS, NROWT);
    ew_split<<<(NPTS * PP / 8 + 255) / 256, 256>>>(pA, nullptr);

    // conv3: out = (h2 @ W3) * m2   [N=512 via 4 column tiles, Kd=128]
    mma_gemm<<<dim3(4, NROWT), 256, SMEM_DYN>>>(phh, PP, nullptr,
        pw3h, PP, out, CH_IN, NPTS, PP, pM2, pPart, CH_IN);
    stats_finalp<<<CH_IN, 256>>>(pPart, CH_IN, NPTS, NROWT);
    ew_final<<<(int)(((size_t)NPTS * CH_IN / 4 + 255) / 256), 256>>>(x, out);
}

// round 16
// speedup vs baseline: 1.0386x; 1.0343x over previous
#include <cuda_runtime.h>
#include <cuda_fp16.h>
#include <cstdint>

#define NPTS 50000
#define CH_IN 512
#define PP 128
#define KNB 27
#define EPSV 1e-5f

typedef __half half_t;

#define NROWT ((NPTS + 127) / 128)   // 391 row tiles

// ---------------- scratch (device globals) ----------------------------------
__device__ float  g_bufA[(size_t)NPTS * PP];
__device__ half_t g_xh[(size_t)NPTS * CH_IN];   // x fp16; reused as t3 fp16 after conv1
__device__ half_t g_hh[(size_t)NPTS * PP];
__device__ half_t g_w1h[PP * CH_IN];        // [128 n][512 k]
__device__ half_t g_w2h[PP * KNB * PP];     // [128 n][3456 k]
__device__ half_t g_w3h[CH_IN * PP];        // [512 n][128 k]
__device__ float  g_ratio[NPTS];
__device__ float  g_m2[NPTS];
__device__ float2 g_part2[(size_t)NROWT * CH_IN];
__device__ float  g_mu[CH_IN];
__device__ float  g_rs[CH_IN];

// ---------------- PTX helpers ------------------------------------------------
__device__ __forceinline__ uint32_t smem_u32(const void* p) {
    uint32_t a;
    asm("{ .reg .u64 t; cvta.to.shared.u64 t, %1; cvt.u32.u64 %0, t; }" : "=r"(a) : "l"(p));
    return a;
}
#define CP16(dst, src) asm volatile("cp.async.cg.shared.global [%0], [%1], 16;" :: "r"(dst), "l"(src) : "memory")
#define CP_COMMIT()    asm volatile("cp.async.commit_group;" ::: "memory")
#define CP_WAIT0()     asm volatile("cp.async.wait_group 0;" ::: "memory")
#define CP_WAIT1()     asm volatile("cp.async.wait_group 1;" ::: "memory")

__device__ __forceinline__ void ldm4(uint32_t* r, uint32_t a) {
    asm volatile("ldmatrix.sync.aligned.m8n8.x4.shared.b16 {%0,%1,%2,%3}, [%4];"
                 : "=r"(r[0]), "=r"(r[1]), "=r"(r[2]), "=r"(r[3]) : "r"(a));
}
__device__ __forceinline__ void mma16816(float* c, const uint32_t* a, const uint32_t* b) {
    asm volatile("mma.sync.aligned.m16n8k16.row.col.f32.f16.f16.f32 "
                 "{%0,%1,%2,%3}, {%4,%5,%6,%7}, {%8,%9}, {%0,%1,%2,%3};"
                 : "+f"(c[0]), "+f"(c[1]), "+f"(c[2]), "+f"(c[3])
                 : "r"(a[0]), "r"(a[1]), "r"(a[2]), "r"(a[3]), "r"(b[0]), "r"(b[1]));
}

// ---------------- fused prep kernel (serial, R13-proven) ----------------------
#define NBR_B  ((NPTS + 255) / 256)
#define XC_B   ((int)(((size_t)NPTS * CH_IN / 4 + 255) / 256))
#define W1E (PP * CH_IN)
#define W2E (PP * KNB * PP)
#define W3E (CH_IN * PP)
#define W_B  ((W1E + W2E + W3E + 255) / 256)

__global__ void prep_all(const float* __restrict__ x, const float* __restrict__ mask,
                         const int* __restrict__ nbr,
                         const float* __restrict__ W1, const float* __restrict__ W2,
                         const float* __restrict__ W3, float* __restrict__ mout) {
    int b = blockIdx.x;
    if (b < NBR_B) {
        int n = b * 256 + threadIdx.x;
        if (n >= NPTS) return;
        float s = 0.f;
#pragma unroll
        for (int k = 0; k < KNB; k++) s += mask[nbr[(size_t)n * KNB + k]];
        float has = s > 0.f ? 1.f : 0.f;
        g_ratio[n] = has * (27.f / fmaxf(s, 1.f));
        g_m2[n] = has;
        mout[n] = fminf(has + mask[n], 1.f);
    } else if (b < NBR_B + XC_B) {
        size_t j = ((size_t)(b - NBR_B) * 256 + threadIdx.x) * 4;
        if (j >= (size_t)NPTS * CH_IN) return;
        float4 v = *(const float4*)(x + j);
        *(half2*)(g_xh + j)     = __floats2half2_rn(v.x, v.y);
        *(half2*)(g_xh + j + 2) = __floats2half2_rn(v.z, v.w);
    } else {
        int i = (b - NBR_B - XC_B) * 256 + threadIdx.x;
        if (i < W1E) {
            int n = i / CH_IN, k = i % CH_IN;
            g_w1h[i] = __float2half_rn(W1[(size_t)k * PP + n]);
        } else if (i < W1E + W2E) {
            int j = i - W1E;
            int n = j / (KNB * PP), kk = j % (KNB * PP);
            g_w2h[j] = __float2half_rn(W2[(size_t)kk * PP + n]);
        } else if (i < W1E + W2E + W3E) {
            int j = i - W1E - W2E;
            int n = j / PP, k = j % PP;
            g_w3h[j] = __float2half_rn(W3[(size_t)k * CH_IN + n]);
        }
    }
}

// ---------------- other small kernels ----------------------------------------
__global__ void stats_finalp(const float2* __restrict__ part, int C, int M, int nslots) {
    int c = blockIdx.x;
    int tid = threadIdx.x;
    float s = 0.f, q = 0.f;
    for (int r = tid; r < nslots; r += 256) {
        float2 v = part[(size_t)r * C + c];
        s += v.x; q += v.y;
    }
    __shared__ float ss[256], sq[256];
    ss[tid] = s; sq[tid] = q;
    __syncthreads();
    for (int d = 128; d > 0; d >>= 1) {
        if (tid < d) { ss[tid] += ss[tid + d]; sq[tid] += sq[tid + d]; }
        __syncthreads();
    }
    if (tid == 0) {
        float mu = ss[0] / (float)M;
        float var = sq[0] / (float)M - mu * mu;
        g_mu[c] = mu;
        g_rs[c] = rsqrtf(fmaxf(var, 0.f) + EPSV);
    }
}
// norm + lrelu (+mask) -> fp16, 4 channels per thread (R13-proven)
__global__ void ew_split(const float* __restrict__ in, const float* __restrict__ mask) {
    int j = (blockIdx.x * blockDim.x + threadIdx.x) * 4;
    if (j >= NPTS * PP) return;
    int c = j & (PP - 1);
    int n = j >> 7;
    float mv = mask ? mask[n] : 1.f;
    float4 v = *(const float4*)(in + j);
    float o0 = (v.x - g_mu[c + 0]) * g_rs[c + 0];
    float o1 = (v.y - g_mu[c + 1]) * g_rs[c + 1];
    float o2 = (v.z - g_mu[c + 2]) * g_rs[c + 2];
    float o3 = (v.w - g_mu[c + 3]) * g_rs[c + 3];
    o0 = (o0 >= 0.f ? o0 : 0.1f * o0) * mv;
    o1 = (o1 >= 0.f ? o1 : 0.1f * o1) * mv;
    o2 = (o2 >= 0.f ? o2 : 0.1f * o2) * mv;
    o3 = (o3 >= 0.f ? o3 : 0.1f * o3) * mv;
    *(half2*)(g_hh + j)     = __floats2half2_rn(o0, o1);
    *(half2*)(g_hh + j + 2) = __floats2half2_rn(o2, o3);
}
// final: out = lrelu(inorm(t3_fp16) + x), 4 channels per thread, vectorized
__global__ void ew_final(const half_t* __restrict__ t3, const float* __restrict__ x,
                         float* __restrict__ outp) {
    size_t j = ((size_t)blockIdx.x * blockDim.x + threadIdx.x) * 4;
    if (j >= (size_t)NPTS * CH_IN) return;
    int c = (int)(j & (CH_IN - 1));
    uint2 hv = *(const uint2*)(t3 + j);          // 4 fp16 values, 8B load
    half2 h0 = *(half2*)&hv.x;
    half2 h1 = *(half2*)&hv.y;
    float4 xv = *(const float4*)(x + j);
    float4 o;
    o.x = (__half2float(h0.x) - g_mu[c + 0]) * g_rs[c + 0] + xv.x;
    o.y = (__half2float(h0.y) - g_mu[c + 1]) * g_rs[c + 1] + xv.y;
    o.z = (__half2float(h1.x) - g_mu[c + 2]) * g_rs[c + 2] + xv.z;
    o.w = (__half2float(h1.y) - g_mu[c + 3]) * g_rs[c + 3] + xv.w;
    o.x = o.x >= 0.f ? o.x : 0.1f * o.x;
    o.y = o.y >= 0.f ? o.y : 0.1f * o.y;
    o.z = o.z >= 0.f ? o.z : 0.1f * o.z;
    o.w = o.w >= 0.f ? o.w : 0.1f * o.w;
    *(float4*)(outp + j) = o;
}

// ---------------- HMMA GEMM (R13 protected config; optional fp16 C) ----------
// C[M,N] = A[M,Kd] @ B[N,Kd]^T, fp16 operands, fp32 acc.
// 128x128 CTA tile, 8 warps of 64x32, K-chunk 64, 3-stage cp.async, 2 CTAs/SM.
// If Ch != null, output stored as fp16 (half2, sector-coalesced); else fp32.
#define STAGE_BYTES 32768
#define OFF_B  16384u
#define OFF_SN (3u * STAGE_BYTES)
#define SMEM_DYN (3 * STAGE_BYTES + 128 * KNB * 4)

__global__ __launch_bounds__(256, 2) void mma_gemm(
    const half_t* __restrict__ Ah, int lda,
    const int* __restrict__ nbr,
    const half_t* __restrict__ Bh, int ldb,
    float* __restrict__ C, half_t* __restrict__ Ch, int ldc, int M, int Kd,
    const float* __restrict__ rowscale,
    float2* __restrict__ part, int partC) {
    extern __shared__ char smem[];
    const uint32_t sb = smem_u32(smem);
    const int tid = threadIdx.x;
    const int row0 = blockIdx.y * 128;
    const int col0 = blockIdx.x * 128;
    int* snbr = (int*)(smem + OFF_SN);

    if (nbr) {
        for (int i = tid; i < 128 * KNB; i += 256) {
            int r = i / KNB, k = i - r * KNB;
            int gr = row0 + r;
            snbr[i] = (gr < M) ? nbr[(size_t)gr * KNB + k] : 0;
        }
        __syncthreads();
    }

    const int w = tid >> 5, l = tid & 31;
    const int wm = (w & 1) * 64, wn = (w >> 1) * 32;
    const int a7 = l & 7;
    const int lkA = (l >> 4) & 1, lkB = (l >> 3) & 1;
    uint32_t aRow[4], bRow[2];
#pragma unroll
    for (int i = 0; i < 4; i++) aRow[i] = (uint32_t)(wm + 16 * i + (l & 15)) << 7;
#pragma unroll
    for (int j = 0; j < 2; j++) bRow[j] = (uint32_t)(wn + 16 * j + (l & 7) + ((l & 16) >> 1)) << 7;

    float acc[4][4][4];
#pragma unroll
    for (int i = 0; i < 4; i++)
#pragma unroll
        for (int n = 0; n < 4; n++)
#pragma unroll
            for (int q = 0; q < 4; q++) acc[i][n][q] = 0.f;

    const int nch = Kd >> 6;

    const int r0i = tid >> 3, seg0 = tid & 7;
    uint32_t swoff[4];
    const half_t* aBase[4];
    const half_t* bBase[4];
#pragma unroll
    for (int p = 0; p < 4; p++) {
        const int r = r0i + p * 32;
        swoff[p] = ((uint32_t)r << 7) + (uint32_t)((seg0 ^ (r & 7)) << 4);
        aBase[p] = Ah + (size_t)min(row0 + r, M - 1) * (size_t)lda + (seg0 << 3);
        bBase[p] = Bh + (size_t)(col0 + r) * (size_t)ldb + (seg0 << 3);
    }

    auto load_chunk = [&](int ch, int stage) {
        const int k0 = ch << 6;
        const int kn = ch >> 1;
        const int c0 = (ch & 1) << 6;
        const uint32_t sbase = sb + (uint32_t)stage * STAGE_BYTES;
#pragma unroll
        for (int p = 0; p < 4; p++) {
            const uint32_t sw = sbase + swoff[p];
            if (nbr) {
                const int r = r0i + p * 32;
                CP16(sw, Ah + (size_t)snbr[r * KNB + kn] * (size_t)lda + c0 + (seg0 << 3));
            } else {
                CP16(sw, aBase[p] + k0);
            }
            CP16(sw + OFF_B, bBase[p] + k0);
        }
    };

    load_chunk(0, 0);
    CP_COMMIT();
    if (nch > 1) { load_chunk(1, 1); CP_COMMIT(); }

    for (int ch = 0; ch < nch; ch++) {
        if (ch + 1 < nch) CP_WAIT1(); else CP_WAIT0();
        __syncthreads();
        if (ch + 2 < nch) { load_chunk(ch + 2, (ch + 2) % 3); CP_COMMIT(); }

        const uint32_t bA = sb + (uint32_t)(ch % 3) * STAGE_BYTES;
#pragma unroll
        for (int s = 0; s < 4; s++) {
            uint32_t ah[4][4], bh[2][4];
            const uint32_t kwA = (uint32_t)((s << 1) | lkA);
            const uint32_t kwB = (uint32_t)((s << 1) | lkB);
#pragma unroll
            for (int i = 0; i < 4; i++)
                ldm4(ah[i], bA + aRow[i] + ((kwA ^ (uint32_t)a7) << 4));
#pragma unroll
            for (int j = 0; j < 2; j++)
                ldm4(bh[j], bA + OFF_B + bRow[j] + ((kwB ^ (uint32_t)a7) << 4));
#pragma unroll
            for (int i = 0; i < 4; i++)
#pragma unroll
                for (int n = 0; n < 4; n++)
                    mma16816(acc[i][n], ah[i], &bh[n >> 1][(n & 1) * 2]);
        }
    }

    // ---- fused epilogue: scale, store (fp32 or fp16), per-CTA column stats ---
    float csum[8], csq[8];
#pragma unroll
    for (int j = 0; j < 8; j++) { csum[j] = 0.f; csq[j] = 0.f; }
#pragma unroll
    for (int i = 0; i < 4; i++) {
#pragma unroll
        for (int hf = 0; hf < 2; hf++) {
            const int r = row0 + wm + 16 * i + 8 * hf + (l >> 2);
            const float sc = (r < M) ? rowscale[r] : 0.f;
            const size_t rowoff = (size_t)r * ldc + col0 + wn + 2 * (l & 3);
#pragma unroll
            for (int n = 0; n < 4; n++) {
                float v0 = acc[i][n][2 * hf] * sc;
                float v1 = acc[i][n][2 * hf + 1] * sc;
                csum[2 * n]     += v0; csq[2 * n]     += v0 * v0;
                csum[2 * n + 1] += v1; csq[2 * n + 1] += v1 * v1;
                if (r < M) {
                    if (Ch) *(half2*)(Ch + rowoff + 8 * n)  = __floats2half2_rn(v0, v1);
                    else    *(float2*)(C + rowoff + 8 * n)  = make_float2(v0, v1);
                }
            }
        }
    }
#pragma unroll
    for (int d = 4; d < 32; d <<= 1) {
#pragma unroll
        for (int j = 0; j < 8; j++) {
            csum[j] += __shfl_xor_sync(0xFFFFFFFFu, csum[j], d);
            csq[j]  += __shfl_xor_sync(0xFFFFFFFFu, csq[j], d);
        }
    }
    float2* red = (float2*)(smem + OFF_SN);
    __syncthreads();
    if (l < 4) {
#pragma unroll
        for (int j = 0; j < 8; j++) {
            int col_local = 8 * (j >> 1) + 2 * l + (j & 1);
            red[w * 32 + col_local] = make_float2(csum[j], csq[j]);
        }
    }
    __syncthreads();
    if (tid < 128) {
        int c = tid, q = c >> 5, lo = c & 31;
        float2 a = red[(2 * q) * 32 + lo];
        float2 b = red[(2 * q + 1) * 32 + lo];
        part[(size_t)blockIdx.y * partC + col0 + c] = make_float2(a.x + b.x, a.y + b.y);
    }
}

// ---------------- launch ------------------------------------------------------
extern "C" void kernel_launch(void* const* d_in, const int* in_sizes, int n_in,
                              void* d_out, int out_size) {
    const float* x    = (const float*)d_in[0];
    const float* mask = (const float*)d_in[1];
    const int*   nbr  = (const int*)d_in[2];
    const float* W1   = (const float*)d_in[3];
    const float* W2   = (const float*)d_in[4];
    const float* W3   = (const float*)d_in[5];
    float* out  = (float*)d_out;
    float* mout = out + (size_t)NPTS * CH_IN;

    cudaFuncSetAttribute(mma_gemm, cudaFuncAttributeMaxDynamicSharedMemorySize, SMEM_DYN);

    float *pA, *pRatio, *pM2;
    float2* pPart;
    half_t *pxh, *phh, *pw1h, *pw2h, *pw3h;
    cudaGetSymbolAddress((void**)&pA, g_bufA);
    cudaGetSymbolAddress((void**)&pRatio, g_ratio);
    cudaGetSymbolAddress((void**)&pM2, g_m2);
    cudaGetSymbolAddress((void**)&pPart, g_part2);
    cudaGetSymbolAddress((void**)&pxh, g_xh);
    cudaGetSymbolAddress((void**)&phh, g_hh);
    cudaGetSymbolAddress((void**)&pw1h, g_w1h);
    cudaGetSymbolAddress((void**)&pw2h, g_w2h);
    cudaGetSymbolAddress((void**)&pw3h, g_w3h);

    // fused prep (serial single stream, R13-proven)
    prep_all<<<NBR_B + XC_B + W_B, 256>>>(x, mask, nbr, W1, W2, W3, mout);

    // conv1: t1 = (x @ W1) * mask   [Kd=512], fp32 out
    mma_gemm<<<dim3(1, NROWT), 256, SMEM_DYN>>>(pxh, CH_IN, nullptr,
        pw1h, CH_IN, pA, nullptr, PP, NPTS, CH_IN, mask, pPart, PP);
    stats_finalp<<<PP, 256>>>(pPart, PP, NPTS, NROWT);
    ew_split<<<(NPTS * PP / 4 + 255) / 256, 256>>>(pA, mask);

    // conv2 gathered: Kd = 27*128 = 3456, fp32 out
    mma_gemm<<<dim3(1, NROWT), 256, SMEM_DYN>>>(phh, PP, nbr,
        pw2h, KNB * PP, pA, nullptr, PP, NPTS, KNB * PP, pRatio, pPart, PP);
    stats_finalp<<<PP, 256>>>(pPart, PP, NPTS, NROWT);
    ew_split<<<(NPTS * PP / 4 + 255) / 256, 256>>>(pA, nullptr);

    // conv3: t3 = (h2 @ W3) * m2  -> fp16 into g_xh (x-fp16 dead after conv1)
    mma_gemm<<<dim3(4, NROWT), 256, SMEM_DYN>>>(phh, PP, nullptr,
        pw3h, PP, nullptr, pxh, CH_IN, NPTS, PP, pM2, pPart, CH_IN);
    stats_finalp<<<CH_IN, 256>>>(pPart, CH_IN, NPTS, NROWT);
    ew_final<<<(int)(((size_t)NPTS * CH_IN / 4 + 255) / 256), 256>>>(pxh, x, out);
}

// round 17
// speedup vs baseline: 1.0467x; 1.0079x over previous
#include <cuda_runtime.h>
#include <cuda_fp16.h>
#include <cstdint>

#define NPTS 50000
#define CH_IN 512
#define PP 128
#define KNB 27
#define EPSV 1e-5f

typedef __half half_t;

#define NROWT ((NPTS + 127) / 128)   // 391 row tiles

// ---------------- scratch (device globals) ----------------------------------
__device__ half_t g_t16[(size_t)NPTS * PP];     // conv1/conv2 outputs (fp16)
__device__ half_t g_xh[(size_t)NPTS * CH_IN];   // x fp16; reused as t3 fp16 after conv1
__device__ half_t g_hh[(size_t)NPTS * PP];
__device__ half_t g_w1h[PP * CH_IN];        // [128 n][512 k]
__device__ half_t g_w2h[PP * KNB * PP];     // [128 n][3456 k]
__device__ half_t g_w3h[CH_IN * PP];        // [512 n][128 k]
__device__ float  g_ratio[NPTS];
__device__ float  g_m2[NPTS];
__device__ float2 g_part2[(size_t)NROWT * CH_IN];
__device__ float  g_mu[CH_IN];
__device__ float  g_rs[CH_IN];

// ---------------- PTX helpers ------------------------------------------------
__device__ __forceinline__ uint32_t smem_u32(const void* p) {
    uint32_t a;
    asm("{ .reg .u64 t; cvta.to.shared.u64 t, %1; cvt.u32.u64 %0, t; }" : "=r"(a) : "l"(p));
    return a;
}
#define CP16(dst, src) asm volatile("cp.async.cg.shared.global [%0], [%1], 16;" :: "r"(dst), "l"(src) : "memory")
#define CP_COMMIT()    asm volatile("cp.async.commit_group;" ::: "memory")
#define CP_WAIT0()     asm volatile("cp.async.wait_group 0;" ::: "memory")
#define CP_WAIT1()     asm volatile("cp.async.wait_group 1;" ::: "memory")

__device__ __forceinline__ void ldm4(uint32_t* r, uint32_t a) {
    asm volatile("ldmatrix.sync.aligned.m8n8.x4.shared.b16 {%0,%1,%2,%3}, [%4];"
                 : "=r"(r[0]), "=r"(r[1]), "=r"(r[2]), "=r"(r[3]) : "r"(a));
}
__device__ __forceinline__ void mma16816(float* c, const uint32_t* a, const uint32_t* b) {
    asm volatile("mma.sync.aligned.m16n8k16.row.col.f32.f16.f16.f32 "
                 "{%0,%1,%2,%3}, {%4,%5,%6,%7}, {%8,%9}, {%0,%1,%2,%3};"
                 : "+f"(c[0]), "+f"(c[1]), "+f"(c[2]), "+f"(c[3])
                 : "r"(a[0]), "r"(a[1]), "r"(a[2]), "r"(a[3]), "r"(b[0]), "r"(b[1]));
}

// ---------------- fused prep kernel (serial, R13-proven) ----------------------
#define NBR_B  ((NPTS + 255) / 256)
#define XC_B   ((int)(((size_t)NPTS * CH_IN / 4 + 255) / 256))
#define W1E (PP * CH_IN)
#define W2E (PP * KNB * PP)
#define W3E (CH_IN * PP)
#define W_B  ((W1E + W2E + W3E + 255) / 256)

__global__ void prep_all(const float* __restrict__ x, const float* __restrict__ mask,
                         const int* __restrict__ nbr,
                         const float* __restrict__ W1, const float* __restrict__ W2,
                         const float* __restrict__ W3, float* __restrict__ mout) {
    int b = blockIdx.x;
    if (b < NBR_B) {
        int n = b * 256 + threadIdx.x;
        if (n >= NPTS) return;
        float s = 0.f;
#pragma unroll
        for (int k = 0; k < KNB; k++) s += mask[nbr[(size_t)n * KNB + k]];
        float has = s > 0.f ? 1.f : 0.f;
        g_ratio[n] = has * (27.f / fmaxf(s, 1.f));
        g_m2[n] = has;
        mout[n] = fminf(has + mask[n], 1.f);
    } else if (b < NBR_B + XC_B) {
        size_t j = ((size_t)(b - NBR_B) * 256 + threadIdx.x) * 4;
        if (j >= (size_t)NPTS * CH_IN) return;
        float4 v = *(const float4*)(x + j);
        *(half2*)(g_xh + j)     = __floats2half2_rn(v.x, v.y);
        *(half2*)(g_xh + j + 2) = __floats2half2_rn(v.z, v.w);
    } else {
        int i = (b - NBR_B - XC_B) * 256 + threadIdx.x;
        if (i < W1E) {
            int n = i / CH_IN, k = i % CH_IN;
            g_w1h[i] = __float2half_rn(W1[(size_t)k * PP + n]);
        } else if (i < W1E + W2E) {
            int j = i - W1E;
            int n = j / (KNB * PP), kk = j % (KNB * PP);
            g_w2h[j] = __float2half_rn(W2[(size_t)kk * PP + n]);
        } else if (i < W1E + W2E + W3E) {
            int j = i - W1E - W2E;
            int n = j / PP, k = j % PP;
            g_w3h[j] = __float2half_rn(W3[(size_t)k * CH_IN + n]);
        }
    }
}

// ---------------- other small kernels ----------------------------------------
__global__ void stats_finalp(const float2* __restrict__ part, int C, int M, int nslots) {
    int c = blockIdx.x;
    int tid = threadIdx.x;
    float s = 0.f, q = 0.f;
    for (int r = tid; r < nslots; r += 256) {
        float2 v = part[(size_t)r * C + c];
        s += v.x; q += v.y;
    }
    __shared__ float ss[256], sq[256];
    ss[tid] = s; sq[tid] = q;
    __syncthreads();
    for (int d = 128; d > 0; d >>= 1) {
        if (tid < d) { ss[tid] += ss[tid + d]; sq[tid] += sq[tid + d]; }
        __syncthreads();
    }
    if (tid == 0) {
        float mu = ss[0] / (float)M;
        float var = sq[0] / (float)M - mu * mu;
        g_mu[c] = mu;
        g_rs[c] = rsqrtf(fmaxf(var, 0.f) + EPSV);
    }
}
// norm + lrelu (+mask): fp16 in (vectorized uint2), fp16 out, 4 ch/thread
__global__ void ew_split(const half_t* __restrict__ in, const float* __restrict__ mask) {
    int j = (blockIdx.x * blockDim.x + threadIdx.x) * 4;
    if (j >= NPTS * PP) return;
    int c = j & (PP - 1);
    int n = j >> 7;
    float mv = mask ? mask[n] : 1.f;
    uint2 hv = *(const uint2*)(in + j);
    half2 h0 = *(half2*)&hv.x;
    half2 h1 = *(half2*)&hv.y;
    float o0 = (__half2float(h0.x) - g_mu[c + 0]) * g_rs[c + 0];
    float o1 = (__half2float(h0.y) - g_mu[c + 1]) * g_rs[c + 1];
    float o2 = (__half2float(h1.x) - g_mu[c + 2]) * g_rs[c + 2];
    float o3 = (__half2float(h1.y) - g_mu[c + 3]) * g_rs[c + 3];
    o0 = (o0 >= 0.f ? o0 : 0.1f * o0) * mv;
    o1 = (o1 >= 0.f ? o1 : 0.1f * o1) * mv;
    o2 = (o2 >= 0.f ? o2 : 0.1f * o2) * mv;
    o3 = (o3 >= 0.f ? o3 : 0.1f * o3) * mv;
    *(half2*)(g_hh + j)     = __floats2half2_rn(o0, o1);
    *(half2*)(g_hh + j + 2) = __floats2half2_rn(o2, o3);
}
// final: out = lrelu(inorm(t3_fp16) + x), 4 channels per thread, vectorized
__global__ void ew_final(const half_t* __restrict__ t3, const float* __restrict__ x,
                         float* __restrict__ outp) {
    size_t j = ((size_t)blockIdx.x * blockDim.x + threadIdx.x) * 4;
    if (j >= (size_t)NPTS * CH_IN) return;
    int c = (int)(j & (CH_IN - 1));
    uint2 hv = *(const uint2*)(t3 + j);
    half2 h0 = *(half2*)&hv.x;
    half2 h1 = *(half2*)&hv.y;
    float4 xv = *(const float4*)(x + j);
    float4 o;
    o.x = (__half2float(h0.x) - g_mu[c + 0]) * g_rs[c + 0] + xv.x;
    o.y = (__half2float(h0.y) - g_mu[c + 1]) * g_rs[c + 1] + xv.y;
    o.z = (__half2float(h1.x) - g_mu[c + 2]) * g_rs[c + 2] + xv.z;
    o.w = (__half2float(h1.y) - g_mu[c + 3]) * g_rs[c + 3] + xv.w;
    o.x = o.x >= 0.f ? o.x : 0.1f * o.x;
    o.y = o.y >= 0.f ? o.y : 0.1f * o.y;
    o.z = o.z >= 0.f ? o.z : 0.1f * o.z;
    o.w = o.w >= 0.f ? o.w : 0.1f * o.w;
    *(float4*)(outp + j) = o;
}

// ---------------- HMMA GEMM (R13 protected config; fp16 C out) ---------------
// C[M,N] = A[M,Kd] @ B[N,Kd]^T, fp16 operands, fp32 acc.
// 128x128 CTA tile, 8 warps of 64x32, K-chunk 64, 3-stage cp.async, 2 CTAs/SM.
// Output stored fp16 (half2, sector-coalesced); stats from fp32 accumulators.
#define STAGE_BYTES 32768
#define OFF_B  16384u
#define OFF_SN (3u * STAGE_BYTES)
#define SMEM_DYN (3 * STAGE_BYTES + 128 * KNB * 4)

__global__ __launch_bounds__(256, 2) void mma_gemm(
    const half_t* __restrict__ Ah, int lda,
    const int* __restrict__ nbr,
    const half_t* __restrict__ Bh, int ldb,
    half_t* __restrict__ Ch, int ldc, int M, int Kd,
    const float* __restrict__ rowscale,
    float2* __restrict__ part, int partC) {
    extern __shared__ char smem[];
    const uint32_t sb = smem_u32(smem);
    const int tid = threadIdx.x;
    const int row0 = blockIdx.y * 128;
    const int col0 = blockIdx.x * 128;
    int* snbr = (int*)(smem + OFF_SN);

    if (nbr) {
        for (int i = tid; i < 128 * KNB; i += 256) {
            int r = i / KNB, k = i - r * KNB;
            int gr = row0 + r;
            snbr[i] = (gr < M) ? nbr[(size_t)gr * KNB + k] : 0;
        }
        __syncthreads();
    }

    const int w = tid >> 5, l = tid & 31;
    const int wm = (w & 1) * 64, wn = (w >> 1) * 32;
    const int a7 = l & 7;
    const int lkA = (l >> 4) & 1, lkB = (l >> 3) & 1;
    uint32_t aRow[4], bRow[2];
#pragma unroll
    for (int i = 0; i < 4; i++) aRow[i] = (uint32_t)(wm + 16 * i + (l & 15)) << 7;
#pragma unroll
    for (int j = 0; j < 2; j++) bRow[j] = (uint32_t)(wn + 16 * j + (l & 7) + ((l & 16) >> 1)) << 7;

    float acc[4][4][4];
#pragma unroll
    for (int i = 0; i < 4; i++)
#pragma unroll
        for (int n = 0; n < 4; n++)
#pragma unroll
            for (int q = 0; q < 4; q++) acc[i][n][q] = 0.f;

    const int nch = Kd >> 6;

    const int r0i = tid >> 3, seg0 = tid & 7;
    uint32_t swoff[4];
    const half_t* aBase[4];
    const half_t* bBase[4];
#pragma unroll
    for (int p = 0; p < 4; p++) {
        const int r = r0i + p * 32;
        swoff[p] = ((uint32_t)r << 7) + (uint32_t)((seg0 ^ (r & 7)) << 4);
        aBase[p] = Ah + (size_t)min(row0 + r, M - 1) * (size_t)lda + (seg0 << 3);
        bBase[p] = Bh + (size_t)(col0 + r) * (size_t)ldb + (seg0 << 3);
    }

    auto load_chunk = [&](int ch, int stage) {
        const int k0 = ch << 6;
        const int kn = ch >> 1;
        const int c0 = (ch & 1) << 6;
        const uint32_t sbase = sb + (uint32_t)stage * STAGE_BYTES;
#pragma unroll
        for (int p = 0; p < 4; p++) {
            const uint32_t sw = sbase + swoff[p];
            if (nbr) {
                const int r = r0i + p * 32;
                CP16(sw, Ah + (size_t)snbr[r * KNB + kn] * (size_t)lda + c0 + (seg0 << 3));
            } else {
                CP16(sw, aBase[p] + k0);
            }
            CP16(sw + OFF_B, bBase[p] + k0);
        }
    };

    load_chunk(0, 0);
    CP_COMMIT();
    if (nch > 1) { load_chunk(1, 1); CP_COMMIT(); }

    for (int ch = 0; ch < nch; ch++) {
        if (ch + 1 < nch) CP_WAIT1(); else CP_WAIT0();
        __syncthreads();
        if (ch + 2 < nch) { load_chunk(ch + 2, (ch + 2) % 3); CP_COMMIT(); }

        const uint32_t bA = sb + (uint32_t)(ch % 3) * STAGE_BYTES;
#pragma unroll
        for (int s = 0; s < 4; s++) {
            uint32_t ah[4][4], bh[2][4];
            const uint32_t kwA = (uint32_t)((s << 1) | lkA);
            const uint32_t kwB = (uint32_t)((s << 1) | lkB);
#pragma unroll
            for (int i = 0; i < 4; i++)
                ldm4(ah[i], bA + aRow[i] + ((kwA ^ (uint32_t)a7) << 4));
#pragma unroll
            for (int j = 0; j < 2; j++)
                ldm4(bh[j], bA + OFF_B + bRow[j] + ((kwB ^ (uint32_t)a7) << 4));
#pragma unroll
            for (int i = 0; i < 4; i++)
#pragma unroll
                for (int n = 0; n < 4; n++)
                    mma16816(acc[i][n], ah[i], &bh[n >> 1][(n & 1) * 2]);
        }
    }

    // ---- fused epilogue: scale, fp16 store, per-CTA column partial stats ----
    float csum[8], csq[8];
#pragma unroll
    for (int j = 0; j < 8; j++) { csum[j] = 0.f; csq[j] = 0.f; }
#pragma unroll
    for (int i = 0; i < 4; i++) {
#pragma unroll
        for (int hf = 0; hf < 2; hf++) {
            const int r = row0 + wm + 16 * i + 8 * hf + (l >> 2);
            const float sc = (r < M) ? rowscale[r] : 0.f;
            half_t* cp = Ch + (size_t)r * ldc + col0 + wn + 2 * (l & 3);
#pragma unroll
            for (int n = 0; n < 4; n++) {
                float v0 = acc[i][n][2 * hf] * sc;
                float v1 = acc[i][n][2 * hf + 1] * sc;
                csum[2 * n]     += v0; csq[2 * n]     += v0 * v0;
                csum[2 * n + 1] += v1; csq[2 * n + 1] += v1 * v1;
                if (r < M) *(half2*)(cp + 8 * n) = __floats2half2_rn(v0, v1);
            }
        }
    }
#pragma unroll
    for (int d = 4; d < 32; d <<= 1) {
#pragma unroll
        for (int j = 0; j < 8; j++) {
            csum[j] += __shfl_xor_sync(0xFFFFFFFFu, csum[j], d);
            csq[j]  += __shfl_xor_sync(0xFFFFFFFFu, csq[j], d);
        }
    }
    float2* red = (float2*)(smem + OFF_SN);
    __syncthreads();
    if (l < 4) {
#pragma unroll
        for (int j = 0; j < 8; j++) {
            int col_local = 8 * (j >> 1) + 2 * l + (j & 1);
            red[w * 32 + col_local] = make_float2(csum[j], csq[j]);
        }
    }
    __syncthreads();
    if (tid < 128) {
        int c = tid, q = c >> 5, lo = c & 31;
        float2 a = red[(2 * q) * 32 + lo];
        float2 b = red[(2 * q + 1) * 32 + lo];
        part[(size_t)blockIdx.y * partC + col0 + c] = make_float2(a.x + b.x, a.y + b.y);
    }
}

// ---------------- launch ------------------------------------------------------
extern "C" void kernel_launch(void* const* d_in, const int* in_sizes, int n_in,
                              void* d_out, int out_size) {
    const float* x    = (const float*)d_in[0];
    const float* mask = (const float*)d_in[1];
    const int*   nbr  = (const int*)d_in[2];
    const float* W1   = (const float*)d_in[3];
    const float* W2   = (const float*)d_in[4];
    const float* W3   = (const float*)d_in[5];
    float* out  = (float*)d_out;
    float* mout = out + (size_t)NPTS * CH_IN;

    cudaFuncSetAttribute(mma_gemm, cudaFuncAttributeMaxDynamicSharedMemorySize, SMEM_DYN);

    float *pRatio, *pM2;
    float2* pPart;
    half_t *pt16, *pxh, *phh, *pw1h, *pw2h, *pw3h;
    cudaGetSymbolAddress((void**)&pt16, g_t16);
    cudaGetSymbolAddress((void**)&pRatio, g_ratio);
    cudaGetSymbolAddress((void**)&pM2, g_m2);
    cudaGetSymbolAddress((void**)&pPart, g_part2);
    cudaGetSymbolAddress((void**)&pxh, g_xh);
    cudaGetSymbolAddress((void**)&phh, g_hh);
    cudaGetSymbolAddress((void**)&pw1h, g_w1h);
    cudaGetSymbolAddress((void**)&pw2h, g_w2h);
    cudaGetSymbolAddress((void**)&pw3h, g_w3h);

    // fused prep (serial single stream, R13-proven)
    prep_all<<<NBR_B + XC_B + W_B, 256>>>(x, mask, nbr, W1, W2, W3, mout);

    // conv1: t1 = (x @ W1) * mask   [Kd=512] -> fp16
    mma_gemm<<<dim3(1, NROWT), 256, SMEM_DYN>>>(pxh, CH_IN, nullptr,
        pw1h, CH_IN, pt16, PP, NPTS, CH_IN, mask, pPart, PP);
    stats_finalp<<<PP, 256>>>(pPart, PP, NPTS, NROWT);
    ew_split<<<(NPTS * PP / 4 + 255) / 256, 256>>>(pt16, mask);

    // conv2 gathered: Kd = 27*128 = 3456 -> fp16
    mma_gemm<<<dim3(1, NROWT), 256, SMEM_DYN>>>(phh, PP, nbr,
        pw2h, KNB * PP, pt16, PP, NPTS, KNB * PP, pRatio, pPart, PP);
    stats_finalp<<<PP, 256>>>(pPart, PP, NPTS, NROWT);
    ew_split<<<(NPTS * PP / 4 + 255) / 256, 256>>>(pt16, nullptr);

    // conv3: t3 = (h2 @ W3) * m2  -> fp16 into g_xh (x-fp16 dead after conv1)
    mma_gemm<<<dim3(4, NROWT), 256, SMEM_DYN>>>(phh, PP, nullptr,
        pw3h, PP, pxh, CH_IN, NPTS, PP, pM2, pPart, CH_IN);
    stats_finalp<<<CH_IN, 256>>>(pPart, CH_IN, NPTS, NROWT);
    ew_final<<<(int)(((size_t)NPTS * CH_IN / 4 + 255) / 256), 256>>>(pxh, x, out);
}